// round 4
// baseline (speedup 1.0000x reference)
#include <cuda_runtime.h>
#include <math.h>

#define NL 6
#define B  8
#define T  4
#define L  2048
#define H  16
#define D  64
#define E  1024
#define FF 4096
#define INDIM 32
#define NTOK 32

#define CPB 96                         // copy blocks appended to host kernels
#define CACHE_F4 50331648LL            // NL*2*B*L*E/4
#define NCHUNK 24
#define CHUNK_F4 (CACHE_F4 / NCHUNK)   // 2097152

// -------- scratch (device globals) --------
__device__ float g_x   [NTOK * E];
__device__ float g_xn  [NTOK * E];
__device__ float g_q   [NTOK * E];
__device__ float g_attn[NTOK * E];
__device__ float g_h   [NTOK * FF];
__device__ float g_seq [NTOK * INDIM];
__device__ float g_part[524288];
__device__ float g_po  [B * H * 4 * T * D];
__device__ float g_m   [B * H * 4 * T];
__device__ float g_l   [B * H * 4 * T];

// -------- f32x2 helpers --------
__device__ __forceinline__ unsigned long long pk2(float lo, float hi) {
    unsigned long long r;
    asm("mov.b64 %0, {%1, %2};" : "=l"(r) : "f"(lo), "f"(hi));
    return r;
}
__device__ __forceinline__ void fma2(unsigned long long& d,
                                     unsigned long long a,
                                     unsigned long long b) {
    asm("fma.rn.f32x2 %0, %1, %2, %3;" : "=l"(d) : "l"(a), "l"(b), "l"(d));
}
__device__ __forceinline__ float2 upk(unsigned long long v) {
    float2 f;
    asm("mov.b64 {%0, %1}, %2;" : "=f"(f.x), "=f"(f.y) : "l"(v));
    return f;
}

// -------- piggyback cache copy: NaN-clean, skip the T new slots --------
// element decode (float4 index): e4 bits0-7, slot bits8-18, b bits19-21,
// kv bit22, l bits23+
__device__ __forceinline__ void copy_range(const float4* __restrict__ in,
                                           float4* __restrict__ out,
                                           const int* __restrict__ allpos,
                                           long long c0, long long c1,
                                           int cb, int ncb)
{
    long long i = c0 + (long long)cb * 256 + threadIdx.x;
    long long stride = (long long)ncb * 256;
    for (; i < c1; i += stride) {
        unsigned slot = ((unsigned)(i >> 8)) & 2047u;
        unsigned b    = ((unsigned)(i >> 19)) & 7u;
        unsigned l    = ((unsigned)(i >> 22)) >> 1;
        int p = allpos[l * 8 + b];
        if ((unsigned)((int)slot - p) < (unsigned)T) continue;   // new slot: owned by scatter
        float4 v = in[i];
        v.x = isnan(v.x) ? 0.0f : v.x;
        v.y = isnan(v.y) ? 0.0f : v.y;
        v.z = isnan(v.z) ? 0.0f : v.z;
        v.w = isnan(v.w) ? 0.0f : v.w;
        out[i] = v;
    }
}

// -------- prep seq (NaN->bos) + new positions, one tiny kernel --------
__global__ void prep_pos_kernel(const float* __restrict__ seq,
                                const float* __restrict__ bos,
                                const int* __restrict__ positions,
                                float* __restrict__ out_seq,
                                float* __restrict__ out_pos)
{
    if (blockIdx.x < 4) {
        int i = blockIdx.x * 256 + threadIdx.x;
        float v = seq[i];
        out_seq[i] = isnan(v) ? bos[i & (INDIM - 1)] : v;
    } else {
        int i = threadIdx.x;
        if (i < NL * B) out_pos[i] = (float)(positions[i] + T);
    }
}

// ======== GEMM: Y[32,N] = X[32,K] @ W[N,K]^T, f32x2, + copy piggyback ======
// flattened grid: (N/64)*KSPLIT compute blocks, then copy blocks.
template<int ACT, int ACC, int KSPLIT>
__global__ void gemv64_kernel(const float* __restrict__ X,
                              const float* __restrict__ W,
                              float* __restrict__ Y,
                              float* __restrict__ part,
                              int K, int N,
                              const float4* __restrict__ cin,
                              float4* __restrict__ cout,
                              const int* __restrict__ allpos,
                              long long c0, long long c1)
{
    __shared__ alignas(16) float Ws[64][36];
    __shared__ alignas(16) unsigned long long XsP[16][33];

    const int nominal = (N >> 6) * KSPLIT;
    if (blockIdx.x >= (unsigned)nominal) {
        copy_range(cin, cout, allpos, c0, c1, blockIdx.x - nominal, gridDim.x - nominal);
        return;
    }
    const int nb = blockIdx.x / KSPLIT;
    const int ks = blockIdx.x - nb * KSPLIT;

    const int t    = threadIdx.x;
    const int lane = t & 31;
    const int c0w  = (t >> 5) * 8;
    const int n0   = nb * 64;
    const int Kc   = K / KSPLIT;
    const int kbase = ks * Kc;
    const int nch  = Kc >> 5;

    const int xrow = t >> 3, xk = (t & 7) * 4;
    const int wrow = t >> 2, wk = (t & 3) * 8;

    const float4* xg = (const float4*)(X + (size_t)xrow * K + kbase + xk);
    const float4* wg = (const float4*)(W + (size_t)(n0 + wrow) * K + kbase + wk);
    float4 xr  = *xg;
    float4 wr0 = wg[0];
    float4 wr1 = wg[1];

    unsigned long long acc[8];
    #pragma unroll
    for (int c = 0; c < 8; c++) acc[c] = 0ULL;

    for (int ch = 0; ch < nch; ch++) {
        XsP[(xk >> 1)    ][xrow] = pk2(xr.x, xr.y);
        XsP[(xk >> 1) + 1][xrow] = pk2(xr.z, xr.w);
        *(float4*)&Ws[wrow][wk]     = wr0;
        *(float4*)&Ws[wrow][wk + 4] = wr1;
        __syncthreads();
        if (ch + 1 < nch) { xg += 8; wg += 8; xr = *xg; wr0 = wg[0]; wr1 = wg[1]; }

        #pragma unroll
        for (int k2 = 0; k2 < 16; k2 += 2) {
            unsigned long long x0 = XsP[k2][lane];
            unsigned long long x1 = XsP[k2 + 1][lane];
            #pragma unroll
            for (int c = 0; c < 8; c++) {
                longlong2 w = *(const longlong2*)&Ws[c0w + c][k2 * 2];
                fma2(acc[c], x0, (unsigned long long)w.x);
                fma2(acc[c], x1, (unsigned long long)w.y);
            }
        }
        __syncthreads();
    }

    if (KSPLIT == 1) {
        #pragma unroll
        for (int c = 0; c < 8; c++) {
            float2 p = upk(acc[c]);
            float v = p.x + p.y;
            if (ACT == 1) v = 0.5f * v * (1.0f + erff(v * 0.70710678118654752f));
            float* pp = Y + (size_t)lane * N + n0 + c0w + c;
            if (ACC) *pp += v; else *pp = v;
        }
    } else {
        float* pp = part + ((size_t)ks * 32 + lane) * N + n0 + c0w;
        #pragma unroll
        for (int c = 0; c < 8; c++) {
            float2 p = upk(acc[c]);
            pp[c] = p.x + p.y;
        }
    }
}

// -------- fused qkv split-K(4) reduce + RoPE + cache scatter --------
__global__ void reduce_rope_kernel(const float* __restrict__ part,
                                   const int* __restrict__ pos_l,
                                   float* __restrict__ qout,
                                   float* __restrict__ kcache,
                                   float* __restrict__ vcache)
{
    int id = blockIdx.x * 256 + threadIdx.x;  // 49152 pairs
    int tok = id / 1536;
    int f2  = id - tok * 1536;
    int f   = f2 * 2;
    float s0 = 0.f, s1 = 0.f;
    #pragma unroll
    for (int k = 0; k < 4; k++) {
        const float* p = part + ((size_t)(k * 32 + tok) * 3072) + f;
        s0 += p[0];
        s1 += p[1];
    }
    int b = tok >> 2, t = tok & 3;
    int pos = pos_l[b];
    if (f < E) {
        int j = (f & 63) >> 1;
        float freq = __expf(-(float)j * (logf(10000.0f) / 32.0f));
        float sn, cs;
        sincosf((float)(pos + t) * freq, &sn, &cs);
        qout[(size_t)tok * E + f]     = s0 * cs - s1 * sn;
        qout[(size_t)tok * E + f + 1] = s0 * sn + s1 * cs;
    } else if (f < 2 * E) {
        int fk = f - E;
        int j = (fk & 63) >> 1;
        float freq = __expf(-(float)j * (logf(10000.0f) / 32.0f));
        float sn, cs;
        sincosf((float)(pos + t) * freq, &sn, &cs);
        int slot = (pos + t) % L;
        size_t off = ((size_t)b * L + slot) * E + fk;
        kcache[off]     = s0 * cs - s1 * sn;
        kcache[off + 1] = s0 * sn + s1 * cs;
    } else {
        int fv = f - 2 * E;
        int slot = (pos + t) % L;
        size_t off = ((size_t)b * L + slot) * E + fv;
        vcache[off]     = s0;
        vcache[off + 1] = s1;
    }
}

// -------- LayerNorm (layer-0 entry only) --------
__global__ void ln_kernel(const float* __restrict__ X,
                          const float* __restrict__ w,
                          const float* __restrict__ b,
                          float* __restrict__ Y)
{
    int tok = blockIdx.x;
    int tid = threadIdx.x;
    const float* x = X + (size_t)tok * E;
    float v[4];
    float s = 0.f;
    #pragma unroll
    for (int j = 0; j < 4; j++) { v[j] = x[tid + 256 * j]; s += v[j]; }
    #pragma unroll
    for (int o = 16; o > 0; o >>= 1) s += __shfl_xor_sync(0xffffffffu, s, o);
    __shared__ float ws[8];
    if ((tid & 31) == 0) ws[tid >> 5] = s;
    __syncthreads();
    float mean = (ws[0]+ws[1]+ws[2]+ws[3]+ws[4]+ws[5]+ws[6]+ws[7]) * (1.0f / E);
    float s2 = 0.f;
    #pragma unroll
    for (int j = 0; j < 4; j++) { float d = v[j] - mean; s2 += d * d; }
    #pragma unroll
    for (int o = 16; o > 0; o >>= 1) s2 += __shfl_xor_sync(0xffffffffu, s2, o);
    __syncthreads();
    if ((tid & 31) == 0) ws[tid >> 5] = s2;
    __syncthreads();
    float var = (ws[0]+ws[1]+ws[2]+ws[3]+ws[4]+ws[5]+ws[6]+ws[7]) * (1.0f / E);
    float r = rsqrtf(var + 1e-5f);
    #pragma unroll
    for (int j = 0; j < 4; j++) {
        int idx = tid + 256 * j;
        Y[(size_t)tok * E + idx] = (v[j] - mean) * r * w[idx] + b[idx];
    }
}

// -------- fused: x += sum(8 split-K partials); xn = LN(x) --------
__global__ void reduce_ln_kernel(const float* __restrict__ part,
                                 float* __restrict__ x,
                                 const float* __restrict__ w,
                                 const float* __restrict__ b,
                                 float* __restrict__ xn)
{
    int tok = blockIdx.x;
    int tid = threadIdx.x;
    float v[4];
    float s = 0.f;
    #pragma unroll
    for (int j = 0; j < 4; j++) {
        int idx = tid + 256 * j;
        float p = 0.f;
        #pragma unroll
        for (int k = 0; k < 8; k++) p += part[((size_t)(k * 32 + tok)) * E + idx];
        float xv = x[(size_t)tok * E + idx] + p;
        x[(size_t)tok * E + idx] = xv;
        v[j] = xv;
        s += xv;
    }
    #pragma unroll
    for (int o = 16; o > 0; o >>= 1) s += __shfl_xor_sync(0xffffffffu, s, o);
    __shared__ float ws[8];
    if ((tid & 31) == 0) ws[tid >> 5] = s;
    __syncthreads();
    float mean = (ws[0]+ws[1]+ws[2]+ws[3]+ws[4]+ws[5]+ws[6]+ws[7]) * (1.0f / E);
    float s2 = 0.f;
    #pragma unroll
    for (int j = 0; j < 4; j++) { float d = v[j] - mean; s2 += d * d; }
    #pragma unroll
    for (int o = 16; o > 0; o >>= 1) s2 += __shfl_xor_sync(0xffffffffu, s2, o);
    __syncthreads();
    if ((tid & 31) == 0) ws[tid >> 5] = s2;
    __syncthreads();
    float var = (ws[0]+ws[1]+ws[2]+ws[3]+ws[4]+ws[5]+ws[6]+ws[7]) * (1.0f / E);
    float r = rsqrtf(var + 1e-5f);
    #pragma unroll
    for (int j = 0; j < 4; j++) {
        int idx = tid + 256 * j;
        xn[(size_t)tok * E + idx] = (v[j] - mean) * r * w[idx] + b[idx];
    }
}

// -------- fused: x += partials; out_x = LN(x); eos dot --------
__global__ void reduce_ln_eos_kernel(const float* __restrict__ part,
                                     float* __restrict__ x,
                                     const float* __restrict__ w,
                                     const float* __restrict__ b,
                                     const float* __restrict__ ew,
                                     const float* __restrict__ eb,
                                     float* __restrict__ Y,
                                     float* __restrict__ out_eos)
{
    int tok = blockIdx.x;
    int tid = threadIdx.x;
    float v[4];
    float s = 0.f;
    #pragma unroll
    for (int j = 0; j < 4; j++) {
        int idx = tid + 256 * j;
        float p = 0.f;
        #pragma unroll
        for (int k = 0; k < 8; k++) p += part[((size_t)(k * 32 + tok)) * E + idx];
        float xv = x[(size_t)tok * E + idx] + p;
        v[j] = xv;
        s += xv;
    }
    #pragma unroll
    for (int o = 16; o > 0; o >>= 1) s += __shfl_xor_sync(0xffffffffu, s, o);
    __shared__ float ws[8];
    if ((tid & 31) == 0) ws[tid >> 5] = s;
    __syncthreads();
    float mean = (ws[0]+ws[1]+ws[2]+ws[3]+ws[4]+ws[5]+ws[6]+ws[7]) * (1.0f / E);
    float s2 = 0.f;
    #pragma unroll
    for (int j = 0; j < 4; j++) { float d = v[j] - mean; s2 += d * d; }
    #pragma unroll
    for (int o = 16; o > 0; o >>= 1) s2 += __shfl_xor_sync(0xffffffffu, s2, o);
    __syncthreads();
    if ((tid & 31) == 0) ws[tid >> 5] = s2;
    __syncthreads();
    float var = (ws[0]+ws[1]+ws[2]+ws[3]+ws[4]+ws[5]+ws[6]+ws[7]) * (1.0f / E);
    float r = rsqrtf(var + 1e-5f);
    float ed = 0.f;
    #pragma unroll
    for (int j = 0; j < 4; j++) {
        int idx = tid + 256 * j;
        float y = (v[j] - mean) * r * w[idx] + b[idx];
        Y[(size_t)tok * E + idx] = y;
        ed += y * ew[idx];
    }
    #pragma unroll
    for (int o = 16; o > 0; o >>= 1) ed += __shfl_xor_sync(0xffffffffu, ed, o);
    __syncthreads();
    if ((tid & 31) == 0) ws[tid >> 5] = ed;
    __syncthreads();
    if (tid == 0)
        out_eos[tok] = ws[0]+ws[1]+ws[2]+ws[3]+ws[4]+ws[5]+ws[6]+ws[7] + eb[0];
}

// -------- Attention partial: 512 compute blocks + copy blocks --------
// old keys/values read from INPUT cache (NaN-cleaned); new T slots from out cache.
#define CMAX 260
__global__ void attn_part_kernel(const float* __restrict__ q,
                                 const float* __restrict__ kin,
                                 const float* __restrict__ vin,
                                 const float* __restrict__ kout,
                                 const float* __restrict__ vout,
                                 const int* __restrict__ pos_l,
                                 float* __restrict__ po,
                                 float* __restrict__ gm,
                                 float* __restrict__ gl,
                                 const float4* __restrict__ cin,
                                 float4* __restrict__ cout,
                                 const int* __restrict__ allpos,
                                 long long cc0, long long cc1)
{
    __shared__ float qs[4][64];
    __shared__ float sc[4][CMAX];
    __shared__ float red[8];
    __shared__ float mt[4], lt[4];
    __shared__ float vpart[4][4][64];

    if (blockIdx.x >= 512) {
        copy_range(cin, cout, allpos, cc0, cc1, blockIdx.x - 512, gridDim.x - 512);
        return;
    }
    int bh   = blockIdx.x & 127;
    int cidx = blockIdx.x >> 7;
    int b = bh >> 4, h = bh & 15;
    int tid = threadIdx.x;
    int pos = pos_l[b];
    int slen = pos + T;
    int chunk = (slen + 3) >> 2;
    int s0 = cidx * chunk;
    int s1 = min(slen, s0 + chunk);
    int len = s1 - s0;
    int gbase = (bh * 4 + cidx) * 4;

    if (len <= 0) {
        po[(size_t)gbase * 64 + tid] = 0.f;
        if (tid < 4) { gm[gbase + tid] = -1e30f; gl[gbase + tid] = 0.f; }
        return;
    }

    {
        int t = tid >> 6, d = tid & 63;
        qs[t][d] = q[((size_t)(b * T + t) * E) + h * D + d];
    }
    __syncthreads();

    const float scale = 0.125f;
    for (int i = tid; i < len; i += 256) {
        int s = s0 + i;
        size_t off = ((size_t)b * L + s) * E + h * D;
        bool old = (s < pos);
        const float4* kr = (const float4*)((old ? kin : kout) + off);
        float d0 = 0.f, d1 = 0.f, d2 = 0.f, d3 = 0.f;
        #pragma unroll
        for (int i4 = 0; i4 < 16; i4++) {
            float4 kv = kr[i4];
            if (old) {
                kv.x = isnan(kv.x) ? 0.f : kv.x;
                kv.y = isnan(kv.y) ? 0.f : kv.y;
                kv.z = isnan(kv.z) ? 0.f : kv.z;
                kv.w = isnan(kv.w) ? 0.f : kv.w;
            }
            int d = i4 * 4;
            d0 += qs[0][d] * kv.x + qs[0][d+1] * kv.y + qs[0][d+2] * kv.z + qs[0][d+3] * kv.w;
            d1 += qs[1][d] * kv.x + qs[1][d+1] * kv.y + qs[1][d+2] * kv.z + qs[1][d+3] * kv.w;
            d2 += qs[2][d] * kv.x + qs[2][d+1] * kv.y + qs[2][d+2] * kv.z + qs[2][d+3] * kv.w;
            d3 += qs[3][d] * kv.x + qs[3][d+1] * kv.y + qs[3][d+2] * kv.z + qs[3][d+3] * kv.w;
        }
        sc[0][i] = (s <= pos + 0) ? d0 * scale : -1e30f;
        sc[1][i] = (s <= pos + 1) ? d1 * scale : -1e30f;
        sc[2][i] = (s <= pos + 2) ? d2 * scale : -1e30f;
        sc[3][i] = (s <= pos + 3) ? d3 * scale : -1e30f;
    }
    __syncthreads();

    #pragma unroll
    for (int t = 0; t < 4; t++) {
        float m = -1e30f;
        for (int i = tid; i < len; i += 256) m = fmaxf(m, sc[t][i]);
        #pragma unroll
        for (int o = 16; o > 0; o >>= 1) m = fmaxf(m, __shfl_xor_sync(0xffffffffu, m, o));
        if ((tid & 31) == 0) red[tid >> 5] = m;
        __syncthreads();
        m = fmaxf(fmaxf(fmaxf(red[0], red[1]), fmaxf(red[2], red[3])),
                  fmaxf(fmaxf(red[4], red[5]), fmaxf(red[6], red[7])));
        float ssum = 0.f;
        for (int i = tid; i < len; i += 256) {
            float e = __expf(sc[t][i] - m);
            sc[t][i] = e;
            ssum += e;
        }
        #pragma unroll
        for (int o = 16; o > 0; o >>= 1) ssum += __shfl_xor_sync(0xffffffffu, ssum, o);
        __syncthreads();
        if ((tid & 31) == 0) red[tid >> 5] = ssum;
        __syncthreads();
        if (tid == 0) {
            mt[t] = m;
            lt[t] = red[0]+red[1]+red[2]+red[3]+red[4]+red[5]+red[6]+red[7];
        }
        __syncthreads();
    }

    {
        int sg = tid >> 6, d = tid & 63;
        int q4 = (len + 3) >> 2;
        int i0 = sg * q4;
        int i1 = min(len, i0 + q4);
        float a0 = 0.f, a1 = 0.f, a2 = 0.f, a3 = 0.f;
        for (int i = i0; i < i1; i++) {
            int s = s0 + i;
            bool old = (s < pos);
            float v0 = (old ? vin : vout)[((size_t)b * L + s) * E + h * D + d];
            if (old) v0 = isnan(v0) ? 0.f : v0;
            a0 += sc[0][i] * v0;
            a1 += sc[1][i] * v0;
            a2 += sc[2][i] * v0;
            a3 += sc[3][i] * v0;
        }
        vpart[sg][0][d] = a0;
        vpart[sg][1][d] = a1;
        vpart[sg][2][d] = a2;
        vpart[sg][3][d] = a3;
    }
    __syncthreads();
    {
        int t = tid >> 6, d = tid & 63;
        float sum = vpart[0][t][d] + vpart[1][t][d] + vpart[2][t][d] + vpart[3][t][d];
        po[((size_t)(gbase + t)) * 64 + d] = sum;
        if (tid < 4) { gm[gbase + tid] = mt[tid]; gl[gbase + tid] = lt[tid]; }
    }
}

// -------- Attention combine --------
__global__ void attn_comb_kernel(const float* __restrict__ po,
                                 const float* __restrict__ gm,
                                 const float* __restrict__ gl,
                                 float* __restrict__ out)
{
    int bh = blockIdx.x;
    int b = bh >> 4, h = bh & 15;
    int tid = threadIdx.x;
    int t = tid >> 6, d = tid & 63;

    float m0 = gm[(bh * 4 + 0) * 4 + t];
    float m1 = gm[(bh * 4 + 1) * 4 + t];
    float m2 = gm[(bh * 4 + 2) * 4 + t];
    float m3 = gm[(bh * 4 + 3) * 4 + t];
    float M = fmaxf(fmaxf(m0, m1), fmaxf(m2, m3));
    float w0 = __expf(m0 - M), w1 = __expf(m1 - M);
    float w2 = __expf(m2 - M), w3 = __expf(m3 - M);
    float l = w0 * gl[(bh * 4 + 0) * 4 + t] + w1 * gl[(bh * 4 + 1) * 4 + t]
            + w2 * gl[(bh * 4 + 2) * 4 + t] + w3 * gl[(bh * 4 + 3) * 4 + t];
    float o = w0 * po[((size_t)(bh * 4 + 0) * 4 + t) * 64 + d]
            + w1 * po[((size_t)(bh * 4 + 1) * 4 + t) * 64 + d]
            + w2 * po[((size_t)(bh * 4 + 2) * 4 + t) * 64 + d]
            + w3 * po[((size_t)(bh * 4 + 3) * 4 + t) * 64 + d];
    out[((size_t)(b * T + t) * E) + h * D + d] = o / l;
}

extern "C" void kernel_launch(void* const* d_in, const int* in_sizes, int n_in,
                              void* d_out, int out_size)
{
    const float* seq       = (const float*)d_in[0];
    const float* bos       = (const float*)d_in[1];
    const float* caches    = (const float*)d_in[2];
    const int*   positions = (const int*)  d_in[3];
    const float* in_w      = (const float*)d_in[4];
    const float* ip_w      = (const float*)d_in[5];
    const float* op_w      = (const float*)d_in[6];
    const float* n1w       = (const float*)d_in[7];
    const float* n1b       = (const float*)d_in[8];
    const float* n2w       = (const float*)d_in[9];
    const float* n2b       = (const float*)d_in[10];
    const float* l1_w      = (const float*)d_in[11];
    const float* l2_w      = (const float*)d_in[12];
    const float* on_w      = (const float*)d_in[13];
    const float* on_b      = (const float*)d_in[14];
    const float* eos_w     = (const float*)d_in[15];
    const float* eos_b     = (const float*)d_in[16];

    float* out = (float*)d_out;
    const size_t cache_elems = (size_t)NL * 2 * B * L * E;
    float* out_x     = out;
    float* out_eos   = out + (size_t)NTOK * E;
    float* out_cache = out_eos + NTOK;
    float* out_pos   = out_cache + cache_elems;

    float *px, *pxn, *pq, *pattn, *ph, *pseq, *ppart, *ppo, *pm, *pl;
    cudaGetSymbolAddress((void**)&px,    g_x);
    cudaGetSymbolAddress((void**)&pxn,   g_xn);
    cudaGetSymbolAddress((void**)&pq,    g_q);
    cudaGetSymbolAddress((void**)&pattn, g_attn);
    cudaGetSymbolAddress((void**)&ph,    g_h);
    cudaGetSymbolAddress((void**)&pseq,  g_seq);
    cudaGetSymbolAddress((void**)&ppart, g_part);
    cudaGetSymbolAddress((void**)&ppo,   g_po);
    cudaGetSymbolAddress((void**)&pm,    g_m);
    cudaGetSymbolAddress((void**)&pl,    g_l);

    const float4* cin = (const float4*)caches;
    float4* cout = (float4*)out_cache;

    prep_pos_kernel<<<5, 256>>>(seq, bos, positions, pseq, out_pos);
    gemv64_kernel<0,0,1><<<E / 64, 256>>>(pseq, in_w, px, nullptr, INDIM, E,
                                          cin, cout, positions, 0, 0);
    ln_kernel<<<NTOK, 256>>>(px, n1w, n1b, pxn);

    long long ck = 0;   // copy chunk cursor
    for (int i = 0; i < NL; i++) {
        const float* ipw = ip_w + (size_t)i * 3 * E * E;
        const float* opw = op_w + (size_t)i * E * E;
        const float* l1  = l1_w + (size_t)i * FF * E;
        const float* l2  = l2_w + (size_t)i * E * FF;
        float* kcache = out_cache + ((size_t)i * 2 + 0) * B * L * E;
        float* vcache = out_cache + ((size_t)i * 2 + 1) * B * L * E;
        const float* kcin = caches + ((size_t)i * 2 + 0) * B * L * E;
        const float* vcin = caches + ((size_t)i * 2 + 1) * B * L * E;
        const int* posl = positions + i * B;

        // qkv: 48*4 compute blocks + copy chunk
        gemv64_kernel<0,0,4><<<48 * 4 + CPB, 256>>>(pxn, ipw, nullptr, ppart, E, 3 * E,
                                                    cin, cout, positions,
                                                    ck * CHUNK_F4, (ck + 1) * CHUNK_F4);
        ck++;
        reduce_rope_kernel<<<192, 256>>>(ppart, posl, pq, kcache, vcache);

        attn_part_kernel<<<512 + CPB, 256>>>(pq, kcin, vcin, kcache, vcache, posl,
                                             ppo, pm, pl,
                                             cin, cout, positions,
                                             ck * CHUNK_F4, (ck + 1) * CHUNK_F4);
        ck++;
        attn_comb_kernel<<<B * H, 256>>>(ppo, pm, pl, pattn);

        // op: K=1024, N=1024, split-K=8
        gemv64_kernel<0,0,8><<<16 * 8, 256>>>(pattn, opw, nullptr, ppart, E, E,
                                              cin, cout, positions, 0, 0);
        reduce_ln_kernel<<<NTOK, 256>>>(ppart, px, n2w + (size_t)i * E, n2b + (size_t)i * E, pxn);

        // l1: K=1024, N=4096, direct gelu + copy chunk
        gemv64_kernel<1,0,1><<<64 + CPB, 256>>>(pxn, l1, ph, nullptr, E, FF,
                                                cin, cout, positions,
                                                ck * CHUNK_F4, (ck + 1) * CHUNK_F4);
        ck++;

        // l2: K=4096, N=1024, split-K=8 + copy chunk
        gemv64_kernel<0,0,8><<<16 * 8 + CPB, 256>>>(ph, l2, nullptr, ppart, FF, E,
                                                    cin, cout, positions,
                                                    ck * CHUNK_F4, (ck + 1) * CHUNK_F4);
        ck++;

        if (i + 1 < NL) {
            reduce_ln_kernel<<<NTOK, 256>>>(ppart, px,
                                            n1w + (size_t)(i + 1) * E,
                                            n1b + (size_t)(i + 1) * E, pxn);
        } else {
            reduce_ln_eos_kernel<<<NTOK, 256>>>(ppart, px, on_w, on_b,
                                                eos_w, eos_b, out_x, out_eos);
        }
    }
}

// round 5
// speedup vs baseline: 1.7471x; 1.7471x over previous
#include <cuda_runtime.h>
#include <math.h>

#define NL 6
#define B  8
#define T  4
#define L  2048
#define H  16
#define D  64
#define E  1024
#define FF 4096
#define INDIM 32
#define NTOK 32

#define CACHE_F4 50331648LL            // NL*2*B*L*E/4

// -------- scratch (device globals) --------
__device__ float g_x   [NTOK * E];
__device__ float g_xn  [NTOK * E];
__device__ float g_q   [NTOK * E];
__device__ float g_attn[NTOK * E];
__device__ float g_h   [NTOK * FF];
__device__ float g_seq [NTOK * INDIM];
__device__ float g_part[524288];
__device__ float g_po  [B * H * 4 * T * D];
__device__ float g_m   [B * H * 4 * T];
__device__ float g_l   [B * H * 4 * T];

// -------- f32x2 helpers --------
__device__ __forceinline__ unsigned long long pk2(float lo, float hi) {
    unsigned long long r;
    asm("mov.b64 %0, {%1, %2};" : "=l"(r) : "f"(lo), "f"(hi));
    return r;
}
__device__ __forceinline__ void fma2(unsigned long long& d,
                                     unsigned long long a,
                                     unsigned long long b) {
    asm("fma.rn.f32x2 %0, %1, %2, %3;" : "=l"(d) : "l"(a), "l"(b), "l"(d));
}
__device__ __forceinline__ float2 upk(unsigned long long v) {
    float2 f;
    asm("mov.b64 {%0, %1}, %2;" : "=f"(f.x), "=f"(f.y) : "l"(v));
    return f;
}

// -------- bulk cache copy (forked stream): NaN-clean, skip the T new slots --------
// float4 index decode: e4 bits0-7, slot bits8-18, b bits19-21, kv bit22, l bits23+
__global__ void cache_copy_kernel(const float4* __restrict__ in,
                                  float4* __restrict__ out,
                                  const int* __restrict__ allpos)
{
    long long i = (long long)blockIdx.x * 256 + threadIdx.x;
    if (i >= CACHE_F4) return;
    unsigned slot = ((unsigned)(i >> 8)) & 2047u;
    unsigned b    = ((unsigned)(i >> 19)) & 7u;
    unsigned l    = ((unsigned)(i >> 22)) >> 1;
    int p = allpos[l * 8 + b];
    if ((unsigned)((int)slot - p) < (unsigned)T) return;   // new slot: owned by scatter
    float4 v = in[i];
    v.x = isnan(v.x) ? 0.0f : v.x;
    v.y = isnan(v.y) ? 0.0f : v.y;
    v.z = isnan(v.z) ? 0.0f : v.z;
    v.w = isnan(v.w) ? 0.0f : v.w;
    out[i] = v;
}

// -------- prep seq (NaN->bos) + new positions --------
__global__ void prep_pos_kernel(const float* __restrict__ seq,
                                const float* __restrict__ bos,
                                const int* __restrict__ positions,
                                float* __restrict__ out_seq,
                                float* __restrict__ out_pos)
{
    if (blockIdx.x < 4) {
        int i = blockIdx.x * 256 + threadIdx.x;
        float v = seq[i];
        out_seq[i] = isnan(v) ? bos[i & (INDIM - 1)] : v;
    } else {
        int i = threadIdx.x;
        if (i < NL * B) out_pos[i] = (float)(positions[i] + T);
    }
}

// ======== GEMM: Y[32,N] = X[32,K] @ W[N,K]^T, f32x2 packed ========
template<int ACT, int ACC, int KSPLIT>
__global__ void gemv64_kernel(const float* __restrict__ X,
                              const float* __restrict__ W,
                              float* __restrict__ Y,
                              float* __restrict__ part,
                              int K, int N)
{
    __shared__ alignas(16) float Ws[64][36];
    __shared__ alignas(16) unsigned long long XsP[16][33];

    const int t    = threadIdx.x;
    const int lane = t & 31;
    const int c0   = (t >> 5) * 8;
    const int n0   = blockIdx.x * 64;
    const int Kc   = K / KSPLIT;
    const int kbase = blockIdx.y * Kc;
    const int nch  = Kc >> 5;

    const int xrow = t >> 3, xk = (t & 7) * 4;
    const int wrow = t >> 2, wk = (t & 3) * 8;

    const float4* xg = (const float4*)(X + (size_t)xrow * K + kbase + xk);
    const float4* wg = (const float4*)(W + (size_t)(n0 + wrow) * K + kbase + wk);
    float4 xr  = *xg;
    float4 wr0 = wg[0];
    float4 wr1 = wg[1];

    unsigned long long acc[8];
    #pragma unroll
    for (int c = 0; c < 8; c++) acc[c] = 0ULL;

    for (int ch = 0; ch < nch; ch++) {
        XsP[(xk >> 1)    ][xrow] = pk2(xr.x, xr.y);
        XsP[(xk >> 1) + 1][xrow] = pk2(xr.z, xr.w);
        *(float4*)&Ws[wrow][wk]     = wr0;
        *(float4*)&Ws[wrow][wk + 4] = wr1;
        __syncthreads();
        if (ch + 1 < nch) { xg += 8; wg += 8; xr = *xg; wr0 = wg[0]; wr1 = wg[1]; }

        #pragma unroll
        for (int k2 = 0; k2 < 16; k2 += 2) {
            unsigned long long x0 = XsP[k2][lane];
            unsigned long long x1 = XsP[k2 + 1][lane];
            #pragma unroll
            for (int c = 0; c < 8; c++) {
                longlong2 w = *(const longlong2*)&Ws[c0 + c][k2 * 2];
                fma2(acc[c], x0, (unsigned long long)w.x);
                fma2(acc[c], x1, (unsigned long long)w.y);
            }
        }
        __syncthreads();
    }

    if (KSPLIT == 1) {
        #pragma unroll
        for (int c = 0; c < 8; c++) {
            float2 p = upk(acc[c]);
            float v = p.x + p.y;
            if (ACT == 1) v = 0.5f * v * (1.0f + erff(v * 0.70710678118654752f));
            float* pp = Y + (size_t)lane * N + n0 + c0 + c;
            if (ACC) *pp += v; else *pp = v;
        }
    } else {
        float* pp = part + ((size_t)blockIdx.y * 32 + lane) * N + n0 + c0;
        #pragma unroll
        for (int c = 0; c < 8; c++) {
            float2 p = upk(acc[c]);
            pp[c] = p.x + p.y;
        }
    }
}

// sum split-K partials, optional gelu / accumulate
template<int ACT, int ACC, int KS>
__global__ void reduce_kernel(const float* __restrict__ part,
                              float* __restrict__ Y, int N)
{
    int i = blockIdx.x * 256 + threadIdx.x;
    if (i >= 32 * N) return;
    int r = i / N, n = i - r * N;
    float s = 0.f;
    #pragma unroll
    for (int k = 0; k < KS; k++) s += part[((size_t)k * 32 + r) * N + n];
    if (ACT == 1) s = 0.5f * s * (1.0f + erff(s * 0.70710678118654752f));
    if (ACC) Y[i] += s; else Y[i] = s;
}

// -------- fused qkv split-K(4) reduce + RoPE + cache scatter --------
__global__ void reduce_rope_kernel(const float* __restrict__ part,
                                   const int* __restrict__ pos_l,
                                   float* __restrict__ qout,
                                   float* __restrict__ kcache,
                                   float* __restrict__ vcache)
{
    int id = blockIdx.x * 256 + threadIdx.x;  // 49152 pairs
    int tok = id / 1536;
    int f2  = id - tok * 1536;
    int f   = f2 * 2;
    float s0 = 0.f, s1 = 0.f;
    #pragma unroll
    for (int k = 0; k < 4; k++) {
        const float* p = part + ((size_t)(k * 32 + tok) * 3072) + f;
        s0 += p[0];
        s1 += p[1];
    }
    int b = tok >> 2, t = tok & 3;
    int pos = pos_l[b];
    if (f < E) {
        int j = (f & 63) >> 1;
        float freq = __expf(-(float)j * (logf(10000.0f) / 32.0f));
        float sn, cs;
        sincosf((float)(pos + t) * freq, &sn, &cs);
        qout[(size_t)tok * E + f]     = s0 * cs - s1 * sn;
        qout[(size_t)tok * E + f + 1] = s0 * sn + s1 * cs;
    } else if (f < 2 * E) {
        int fk = f - E;
        int j = (fk & 63) >> 1;
        float freq = __expf(-(float)j * (logf(10000.0f) / 32.0f));
        float sn, cs;
        sincosf((float)(pos + t) * freq, &sn, &cs);
        int slot = (pos + t) % L;
        size_t off = ((size_t)b * L + slot) * E + fk;
        kcache[off]     = s0 * cs - s1 * sn;
        kcache[off + 1] = s0 * sn + s1 * cs;
    } else {
        int fv = f - 2 * E;
        int slot = (pos + t) % L;
        size_t off = ((size_t)b * L + slot) * E + fv;
        vcache[off]     = s0;
        vcache[off + 1] = s1;
    }
}

// -------- LayerNorm (layer-0 entry only) --------
__global__ void ln_kernel(const float* __restrict__ X,
                          const float* __restrict__ w,
                          const float* __restrict__ b,
                          float* __restrict__ Y)
{
    int tok = blockIdx.x;
    int tid = threadIdx.x;
    const float* x = X + (size_t)tok * E;
    float v[4];
    float s = 0.f;
    #pragma unroll
    for (int j = 0; j < 4; j++) { v[j] = x[tid + 256 * j]; s += v[j]; }
    #pragma unroll
    for (int o = 16; o > 0; o >>= 1) s += __shfl_xor_sync(0xffffffffu, s, o);
    __shared__ float ws[8];
    if ((tid & 31) == 0) ws[tid >> 5] = s;
    __syncthreads();
    float mean = (ws[0]+ws[1]+ws[2]+ws[3]+ws[4]+ws[5]+ws[6]+ws[7]) * (1.0f / E);
    float s2 = 0.f;
    #pragma unroll
    for (int j = 0; j < 4; j++) { float d = v[j] - mean; s2 += d * d; }
    #pragma unroll
    for (int o = 16; o > 0; o >>= 1) s2 += __shfl_xor_sync(0xffffffffu, s2, o);
    __syncthreads();
    if ((tid & 31) == 0) ws[tid >> 5] = s2;
    __syncthreads();
    float var = (ws[0]+ws[1]+ws[2]+ws[3]+ws[4]+ws[5]+ws[6]+ws[7]) * (1.0f / E);
    float r = rsqrtf(var + 1e-5f);
    #pragma unroll
    for (int j = 0; j < 4; j++) {
        int idx = tid + 256 * j;
        Y[(size_t)tok * E + idx] = (v[j] - mean) * r * w[idx] + b[idx];
    }
}

// -------- fused: x += sum(8 split-K partials); xn = LN(x) --------
__global__ void reduce_ln_kernel(const float* __restrict__ part,
                                 float* __restrict__ x,
                                 const float* __restrict__ w,
                                 const float* __restrict__ b,
                                 float* __restrict__ xn)
{
    int tok = blockIdx.x;
    int tid = threadIdx.x;
    float v[4];
    float s = 0.f;
    #pragma unroll
    for (int j = 0; j < 4; j++) {
        int idx = tid + 256 * j;
        float p = 0.f;
        #pragma unroll
        for (int k = 0; k < 8; k++) p += part[((size_t)(k * 32 + tok)) * E + idx];
        float xv = x[(size_t)tok * E + idx] + p;
        x[(size_t)tok * E + idx] = xv;
        v[j] = xv;
        s += xv;
    }
    #pragma unroll
    for (int o = 16; o > 0; o >>= 1) s += __shfl_xor_sync(0xffffffffu, s, o);
    __shared__ float ws[8];
    if ((tid & 31) == 0) ws[tid >> 5] = s;
    __syncthreads();
    float mean = (ws[0]+ws[1]+ws[2]+ws[3]+ws[4]+ws[5]+ws[6]+ws[7]) * (1.0f / E);
    float s2 = 0.f;
    #pragma unroll
    for (int j = 0; j < 4; j++) { float d = v[j] - mean; s2 += d * d; }
    #pragma unroll
    for (int o = 16; o > 0; o >>= 1) s2 += __shfl_xor_sync(0xffffffffu, s2, o);
    __syncthreads();
    if ((tid & 31) == 0) ws[tid >> 5] = s2;
    __syncthreads();
    float var = (ws[0]+ws[1]+ws[2]+ws[3]+ws[4]+ws[5]+ws[6]+ws[7]) * (1.0f / E);
    float r = rsqrtf(var + 1e-5f);
    #pragma unroll
    for (int j = 0; j < 4; j++) {
        int idx = tid + 256 * j;
        xn[(size_t)tok * E + idx] = (v[j] - mean) * r * w[idx] + b[idx];
    }
}

// -------- fused: x += partials; out_x = LN(x); eos dot --------
__global__ void reduce_ln_eos_kernel(const float* __restrict__ part,
                                     float* __restrict__ x,
                                     const float* __restrict__ w,
                                     const float* __restrict__ b,
                                     const float* __restrict__ ew,
                                     const float* __restrict__ eb,
                                     float* __restrict__ Y,
                                     float* __restrict__ out_eos)
{
    int tok = blockIdx.x;
    int tid = threadIdx.x;
    float v[4];
    float s = 0.f;
    #pragma unroll
    for (int j = 0; j < 4; j++) {
        int idx = tid + 256 * j;
        float p = 0.f;
        #pragma unroll
        for (int k = 0; k < 8; k++) p += part[((size_t)(k * 32 + tok)) * E + idx];
        float xv = x[(size_t)tok * E + idx] + p;
        v[j] = xv;
        s += xv;
    }
    #pragma unroll
    for (int o = 16; o > 0; o >>= 1) s += __shfl_xor_sync(0xffffffffu, s, o);
    __shared__ float ws[8];
    if ((tid & 31) == 0) ws[tid >> 5] = s;
    __syncthreads();
    float mean = (ws[0]+ws[1]+ws[2]+ws[3]+ws[4]+ws[5]+ws[6]+ws[7]) * (1.0f / E);
    float s2 = 0.f;
    #pragma unroll
    for (int j = 0; j < 4; j++) { float d = v[j] - mean; s2 += d * d; }
    #pragma unroll
    for (int o = 16; o > 0; o >>= 1) s2 += __shfl_xor_sync(0xffffffffu, s2, o);
    __syncthreads();
    if ((tid & 31) == 0) ws[tid >> 5] = s2;
    __syncthreads();
    float var = (ws[0]+ws[1]+ws[2]+ws[3]+ws[4]+ws[5]+ws[6]+ws[7]) * (1.0f / E);
    float r = rsqrtf(var + 1e-5f);
    float ed = 0.f;
    #pragma unroll
    for (int j = 0; j < 4; j++) {
        int idx = tid + 256 * j;
        float y = (v[j] - mean) * r * w[idx] + b[idx];
        Y[(size_t)tok * E + idx] = y;
        ed += y * ew[idx];
    }
    #pragma unroll
    for (int o = 16; o > 0; o >>= 1) ed += __shfl_xor_sync(0xffffffffu, ed, o);
    __syncthreads();
    if ((tid & 31) == 0) ws[tid >> 5] = ed;
    __syncthreads();
    if (tid == 0)
        out_eos[tok] = ws[0]+ws[1]+ws[2]+ws[3]+ws[4]+ws[5]+ws[6]+ws[7] + eb[0];
}

// -------- Attention partial: old K/V from INPUT cache (NaN-clean inline),
//          new T slots from output cache (scattered). Independent of bulk copy.
#define CMAX 260
__global__ void attn_part_kernel(const float* __restrict__ q,
                                 const float* __restrict__ kin,
                                 const float* __restrict__ vin,
                                 const float* __restrict__ kout,
                                 const float* __restrict__ vout,
                                 const int* __restrict__ pos_l,
                                 float* __restrict__ po,
                                 float* __restrict__ gm,
                                 float* __restrict__ gl)
{
    __shared__ float qs[4][64];
    __shared__ float sc[4][CMAX];
    __shared__ float red[8];
    __shared__ float mt[4], lt[4];
    __shared__ float vpart[4][4][64];

    int bh   = blockIdx.x & 127;
    int cidx = blockIdx.x >> 7;
    int b = bh >> 4, h = bh & 15;
    int tid = threadIdx.x;
    int pos = pos_l[b];
    int slen = pos + T;
    int chunk = (slen + 3) >> 2;
    int s0 = cidx * chunk;
    int s1 = min(slen, s0 + chunk);
    int len = s1 - s0;
    int gbase = (bh * 4 + cidx) * 4;

    if (len <= 0) {
        po[(size_t)gbase * 64 + tid] = 0.f;
        if (tid < 4) { gm[gbase + tid] = -1e30f; gl[gbase + tid] = 0.f; }
        return;
    }

    {
        int t = tid >> 6, d = tid & 63;
        qs[t][d] = q[((size_t)(b * T + t) * E) + h * D + d];
    }
    __syncthreads();

    const float scale = 0.125f;
    for (int i = tid; i < len; i += 256) {
        int s = s0 + i;
        size_t off = ((size_t)b * L + s) * E + h * D;
        bool old = (s < pos);
        const float4* kr = (const float4*)((old ? kin : kout) + off);
        float d0 = 0.f, d1 = 0.f, d2 = 0.f, d3 = 0.f;
        #pragma unroll
        for (int i4 = 0; i4 < 16; i4++) {
            float4 kv = kr[i4];
            if (old) {
                kv.x = isnan(kv.x) ? 0.f : kv.x;
                kv.y = isnan(kv.y) ? 0.f : kv.y;
                kv.z = isnan(kv.z) ? 0.f : kv.z;
                kv.w = isnan(kv.w) ? 0.f : kv.w;
            }
            int d = i4 * 4;
            d0 += qs[0][d] * kv.x + qs[0][d+1] * kv.y + qs[0][d+2] * kv.z + qs[0][d+3] * kv.w;
            d1 += qs[1][d] * kv.x + qs[1][d+1] * kv.y + qs[1][d+2] * kv.z + qs[1][d+3] * kv.w;
            d2 += qs[2][d] * kv.x + qs[2][d+1] * kv.y + qs[2][d+2] * kv.z + qs[2][d+3] * kv.w;
            d3 += qs[3][d] * kv.x + qs[3][d+1] * kv.y + qs[3][d+2] * kv.z + qs[3][d+3] * kv.w;
        }
        sc[0][i] = (s <= pos + 0) ? d0 * scale : -1e30f;
        sc[1][i] = (s <= pos + 1) ? d1 * scale : -1e30f;
        sc[2][i] = (s <= pos + 2) ? d2 * scale : -1e30f;
        sc[3][i] = (s <= pos + 3) ? d3 * scale : -1e30f;
    }
    __syncthreads();

    #pragma unroll
    for (int t = 0; t < 4; t++) {
        float m = -1e30f;
        for (int i = tid; i < len; i += 256) m = fmaxf(m, sc[t][i]);
        #pragma unroll
        for (int o = 16; o > 0; o >>= 1) m = fmaxf(m, __shfl_xor_sync(0xffffffffu, m, o));
        if ((tid & 31) == 0) red[tid >> 5] = m;
        __syncthreads();
        m = fmaxf(fmaxf(fmaxf(red[0], red[1]), fmaxf(red[2], red[3])),
                  fmaxf(fmaxf(red[4], red[5]), fmaxf(red[6], red[7])));
        float ssum = 0.f;
        for (int i = tid; i < len; i += 256) {
            float e = __expf(sc[t][i] - m);
            sc[t][i] = e;
            ssum += e;
        }
        #pragma unroll
        for (int o = 16; o > 0; o >>= 1) ssum += __shfl_xor_sync(0xffffffffu, ssum, o);
        __syncthreads();
        if ((tid & 31) == 0) red[tid >> 5] = ssum;
        __syncthreads();
        if (tid == 0) {
            mt[t] = m;
            lt[t] = red[0]+red[1]+red[2]+red[3]+red[4]+red[5]+red[6]+red[7];
        }
        __syncthreads();
    }

    {
        int sg = tid >> 6, d = tid & 63;
        int q4 = (len + 3) >> 2;
        int i0 = sg * q4;
        int i1 = min(len, i0 + q4);
        float a0 = 0.f, a1 = 0.f, a2 = 0.f, a3 = 0.f;
        for (int i = i0; i < i1; i++) {
            int s = s0 + i;
            bool old = (s < pos);
            float v0 = (old ? vin : vout)[((size_t)b * L + s) * E + h * D + d];
            if (old) v0 = isnan(v0) ? 0.f : v0;
            a0 += sc[0][i] * v0;
            a1 += sc[1][i] * v0;
            a2 += sc[2][i] * v0;
            a3 += sc[3][i] * v0;
        }
        vpart[sg][0][d] = a0;
        vpart[sg][1][d] = a1;
        vpart[sg][2][d] = a2;
        vpart[sg][3][d] = a3;
    }
    __syncthreads();
    {
        int t = tid >> 6, d = tid & 63;
        float sum = vpart[0][t][d] + vpart[1][t][d] + vpart[2][t][d] + vpart[3][t][d];
        po[((size_t)(gbase + t)) * 64 + d] = sum;
        if (tid < 4) { gm[gbase + tid] = mt[tid]; gl[gbase + tid] = lt[tid]; }
    }
}

// -------- Attention combine --------
__global__ void attn_comb_kernel(const float* __restrict__ po,
                                 const float* __restrict__ gm,
                                 const float* __restrict__ gl,
                                 float* __restrict__ out)
{
    int bh = blockIdx.x;
    int b = bh >> 4, h = bh & 15;
    int tid = threadIdx.x;
    int t = tid >> 6, d = tid & 63;

    float m0 = gm[(bh * 4 + 0) * 4 + t];
    float m1 = gm[(bh * 4 + 1) * 4 + t];
    float m2 = gm[(bh * 4 + 2) * 4 + t];
    float m3 = gm[(bh * 4 + 3) * 4 + t];
    float M = fmaxf(fmaxf(m0, m1), fmaxf(m2, m3));
    float w0 = __expf(m0 - M), w1 = __expf(m1 - M);
    float w2 = __expf(m2 - M), w3 = __expf(m3 - M);
    float l = w0 * gl[(bh * 4 + 0) * 4 + t] + w1 * gl[(bh * 4 + 1) * 4 + t]
            + w2 * gl[(bh * 4 + 2) * 4 + t] + w3 * gl[(bh * 4 + 3) * 4 + t];
    float o = w0 * po[((size_t)(bh * 4 + 0) * 4 + t) * 64 + d]
            + w1 * po[((size_t)(bh * 4 + 1) * 4 + t) * 64 + d]
            + w2 * po[((size_t)(bh * 4 + 2) * 4 + t) * 64 + d]
            + w3 * po[((size_t)(bh * 4 + 3) * 4 + t) * 64 + d];
    out[((size_t)(b * T + t) * E) + h * D + d] = o / l;
}

extern "C" void kernel_launch(void* const* d_in, const int* in_sizes, int n_in,
                              void* d_out, int out_size)
{
    const float* seq       = (const float*)d_in[0];
    const float* bos       = (const float*)d_in[1];
    const float* caches    = (const float*)d_in[2];
    const int*   positions = (const int*)  d_in[3];
    const float* in_w      = (const float*)d_in[4];
    const float* ip_w      = (const float*)d_in[5];
    const float* op_w      = (const float*)d_in[6];
    const float* n1w       = (const float*)d_in[7];
    const float* n1b       = (const float*)d_in[8];
    const float* n2w       = (const float*)d_in[9];
    const float* n2b       = (const float*)d_in[10];
    const float* l1_w      = (const float*)d_in[11];
    const float* l2_w      = (const float*)d_in[12];
    const float* on_w      = (const float*)d_in[13];
    const float* on_b      = (const float*)d_in[14];
    const float* eos_w     = (const float*)d_in[15];
    const float* eos_b     = (const float*)d_in[16];

    float* out = (float*)d_out;
    const size_t cache_elems = (size_t)NL * 2 * B * L * E;
    float* out_x     = out;
    float* out_eos   = out + (size_t)NTOK * E;
    float* out_cache = out_eos + NTOK;
    float* out_pos   = out_cache + cache_elems;

    float *px, *pxn, *pq, *pattn, *ph, *pseq, *ppart, *ppo, *pm, *pl;
    cudaGetSymbolAddress((void**)&px,    g_x);
    cudaGetSymbolAddress((void**)&pxn,   g_xn);
    cudaGetSymbolAddress((void**)&pq,    g_q);
    cudaGetSymbolAddress((void**)&pattn, g_attn);
    cudaGetSymbolAddress((void**)&ph,    g_h);
    cudaGetSymbolAddress((void**)&pseq,  g_seq);
    cudaGetSymbolAddress((void**)&ppart, g_part);
    cudaGetSymbolAddress((void**)&ppo,   g_po);
    cudaGetSymbolAddress((void**)&pm,    g_m);
    cudaGetSymbolAddress((void**)&pl,    g_l);

    // ---- fork: bulk cache copy runs concurrently on a side stream ----
    cudaStream_t cs;
    cudaStreamCreateWithFlags(&cs, cudaStreamNonBlocking);
    cudaEvent_t evFork, evJoin;
    cudaEventCreateWithFlags(&evFork, cudaEventDisableTiming);
    cudaEventCreateWithFlags(&evJoin, cudaEventDisableTiming);

    cudaEventRecord(evFork, 0);
    cudaStreamWaitEvent(cs, evFork, 0);
    cache_copy_kernel<<<(unsigned)((CACHE_F4 + 255) / 256), 256, 0, cs>>>(
        (const float4*)caches, (float4*)out_cache, positions);
    cudaEventRecord(evJoin, cs);

    // ---- compute chain on main stream (independent of bulk copy) ----
    prep_pos_kernel<<<5, 256>>>(seq, bos, positions, pseq, out_pos);
    gemv64_kernel<0,0,1><<<E / 64, 256>>>(pseq, in_w, px, nullptr, INDIM, E);
    ln_kernel<<<NTOK, 256>>>(px, n1w, n1b, pxn);

    for (int i = 0; i < NL; i++) {
        const float* ipw = ip_w + (size_t)i * 3 * E * E;
        const float* opw = op_w + (size_t)i * E * E;
        const float* l1  = l1_w + (size_t)i * FF * E;
        const float* l2  = l2_w + (size_t)i * E * FF;
        float* kcache = out_cache + ((size_t)i * 2 + 0) * B * L * E;
        float* vcache = out_cache + ((size_t)i * 2 + 1) * B * L * E;
        const float* kcin = caches + ((size_t)i * 2 + 0) * B * L * E;
        const float* vcin = caches + ((size_t)i * 2 + 1) * B * L * E;
        const int* posl = positions + i * B;

        // qkv: K=1024, N=3072, split-K=4 -> 192 blocks
        gemv64_kernel<0,0,4><<<dim3(3 * E / 64, 4), 256>>>(pxn, ipw, nullptr, ppart, E, 3 * E);
        reduce_rope_kernel<<<192, 256>>>(ppart, posl, pq, kcache, vcache);

        attn_part_kernel<<<512, 256>>>(pq, kcin, vcin, kcache, vcache, posl, ppo, pm, pl);
        attn_comb_kernel<<<B * H, 256>>>(ppo, pm, pl, pattn);

        // op: K=1024, N=1024, split-K=8 -> 128 blocks; fused reduce+add+LN
        gemv64_kernel<0,0,8><<<dim3(E / 64, 8), 256>>>(pattn, opw, nullptr, ppart, E, E);
        reduce_ln_kernel<<<NTOK, 256>>>(ppart, px, n2w + (size_t)i * E, n2b + (size_t)i * E, pxn);

        // l1: K=1024, N=4096, split-K=2 -> 128 blocks; gelu in reduce
        gemv64_kernel<0,0,2><<<dim3(FF / 64, 2), 256>>>(pxn, l1, nullptr, ppart, E, FF);
        reduce_kernel<1,0,2><<<(32 * FF + 255) / 256, 256>>>(ppart, ph, FF);

        // l2: K=4096, N=1024, split-K=8 -> 128 blocks; fused reduce+add+LN (or final)
        gemv64_kernel<0,0,8><<<dim3(E / 64, 8), 256>>>(ph, l2, nullptr, ppart, FF, E);
        if (i + 1 < NL) {
            reduce_ln_kernel<<<NTOK, 256>>>(ppart, px,
                                            n1w + (size_t)(i + 1) * E,
                                            n1b + (size_t)(i + 1) * E, pxn);
        } else {
            reduce_ln_eos_kernel<<<NTOK, 256>>>(ppart, px, on_w, on_b,
                                                eos_w, eos_b, out_x, out_eos);
        }
    }

    // ---- join: copy must complete before the graph's end ----
    cudaStreamWaitEvent(0, evJoin, 0);
}